// round 4
// baseline (speedup 1.0000x reference)
#include <cuda_runtime.h>
#include <cuda_fp16.h>
#include <math.h>

#define NTYPES 10000
#define NG     2000
#define NB     1024

// ---------------- scratch (device globals; no allocation allowed) ----------------
__device__ __half g_IWh[NTYPES * 128];   // impact @ W.T   (fp16)
__device__ __half g_IMh[NTYPES * 128];   // impact @ M.T   (fp16)
__device__ __half g_W1h[128 * 256];      // W1 in fp16
__device__ float  g_E [NG * 128];        // softmax(per_graph)
__device__ float  g_X [NG * 128];        // softmax(relu(ext))

__device__ __forceinline__ float4 ldh4(const __half* p) {
    const uint2 r = *(const uint2*)p;
    const float2 lo = __half22float2(*(const __half2*)&r.x);
    const float2 hi = __half22float2(*(const __half2*)&r.y);
    return make_float4(lo.x, lo.y, hi.x, hi.y);
}

// ---- Blackwell packed f32x2 helpers ----
typedef unsigned long long u64t;
__device__ __forceinline__ u64t pk2(float lo, float hi) {
    u64t r;
    asm("mov.b64 %0, {%1, %2};" : "=l"(r) : "r"(__float_as_uint(lo)), "r"(__float_as_uint(hi)));
    return r;
}
__device__ __forceinline__ float2 upk2(u64t v) {
    unsigned lo, hi;
    asm("mov.b64 {%0, %1}, %2;" : "=r"(lo), "=r"(hi) : "l"(v));
    return make_float2(__uint_as_float(lo), __uint_as_float(hi));
}
#define FMA2(d, a, b) asm("fma.rn.f32x2 %0, %1, %2, %0;" : "+l"(d) : "l"(a), "l"(b))

// ============================================================================
// Kernel A: IW = impact @ W.T, IM = impact @ M.T  -> fp16 tables (f32x2 math)
// Blocks 0..15 additionally convert W1 -> g_W1h.
// ============================================================================
#define A_WSTR 132
#define A_ASTR 68
#define SMEM_A ((2 * 128 * A_WSTR + 128 * A_ASTR) * 4)

__global__ void __launch_bounds__(256) kA(const float* __restrict__ impact,
                                          const float* __restrict__ W,
                                          const float* __restrict__ M,
                                          const float* __restrict__ W1) {
    extern __shared__ float sm[];
    float* sWt = sm;                       // [128][A_WSTR]  Wt[i][j] = W[j][i]
    float* sMt = sm + 128 * A_WSTR;
    float* sAt = sm + 2 * 128 * A_WSTR;    // [128][A_ASTR]  At[i][r]

    const int tid = threadIdx.x;
    const int rowBase = blockIdx.x * 64;

    // side job: W1 -> fp16 (32768 elements over 16 blocks)
    if (blockIdx.x < 16) {
        const int base = blockIdx.x * 2048;
        for (int q = tid; q < 1024; q += 256) {
            const float2 v = *(const float2*)(W1 + base + (q << 1));
            *(__half2*)(g_W1h + base + (q << 1)) = __floats2half2_rn(v.x, v.y);
        }
    }

    for (int idx = tid; idx < 128 * 128; idx += 256) {
        int j = idx >> 7, i = idx & 127;
        sWt[i * A_WSTR + j] = W[idx];
        sMt[i * A_WSTR + j] = M[idx];
    }
    for (int idx = tid; idx < 64 * 128; idx += 256) {
        int r = idx >> 7, i = idx & 127;
        int row = rowBase + r;
        sAt[i * A_ASTR + r] = (row < NTYPES) ? impact[row * 128 + i] : 0.f;
    }
    __syncthreads();

    const int tx = tid & 31;   // 4-col group
    const int ty = tid >> 5;   // 8-row group
    u64t accW2[4][4] = {};     // [rr-pair][cc]
    u64t accM2[4][4] = {};

#pragma unroll 4
    for (int i = 0; i < 128; ++i) {
        const float4 wv = *(const float4*)(sWt + i * A_WSTR + (tx << 2));
        const float4 mv = *(const float4*)(sMt + i * A_WSTR + (tx << 2));
        const float4 a0 = *(const float4*)(sAt + i * A_ASTR + (ty << 3));
        const float4 a1 = *(const float4*)(sAt + i * A_ASTR + (ty << 3) + 4);
        u64t ap[4], wd[4], md[4];
        ap[0] = pk2(a0.x, a0.y); ap[1] = pk2(a0.z, a0.w);
        ap[2] = pk2(a1.x, a1.y); ap[3] = pk2(a1.z, a1.w);
        wd[0] = pk2(wv.x, wv.x); wd[1] = pk2(wv.y, wv.y);
        wd[2] = pk2(wv.z, wv.z); wd[3] = pk2(wv.w, wv.w);
        md[0] = pk2(mv.x, mv.x); md[1] = pk2(mv.y, mv.y);
        md[2] = pk2(mv.z, mv.z); md[3] = pk2(mv.w, mv.w);
#pragma unroll
        for (int rp = 0; rp < 4; ++rp) {
#pragma unroll
            for (int cc = 0; cc < 4; ++cc) {
                FMA2(accW2[rp][cc], ap[rp], wd[cc]);
                FMA2(accM2[rp][cc], ap[rp], md[cc]);
            }
        }
    }

#pragma unroll
    for (int rp = 0; rp < 4; ++rp) {
        float2 w0 = upk2(accW2[rp][0]), w1 = upk2(accW2[rp][1]);
        float2 w2 = upk2(accW2[rp][2]), w3 = upk2(accW2[rp][3]);
        float2 m0 = upk2(accM2[rp][0]), m1 = upk2(accM2[rp][1]);
        float2 m2 = upk2(accM2[rp][2]), m3 = upk2(accM2[rp][3]);
#pragma unroll
        for (int h = 0; h < 2; ++h) {
            const int row = rowBase + (ty << 3) + (rp << 1) + h;
            if (row < NTYPES) {
                const float cw[4] = {h ? w0.y : w0.x, h ? w1.y : w1.x,
                                     h ? w2.y : w2.x, h ? w3.y : w3.x};
                const float cm[4] = {h ? m0.y : m0.x, h ? m1.y : m1.x,
                                     h ? m2.y : m2.x, h ? m3.y : m3.x};
                __half2 wA = __floats2half2_rn(cw[0], cw[1]);
                __half2 wB = __floats2half2_rn(cw[2], cw[3]);
                __half2 mA = __floats2half2_rn(cm[0], cm[1]);
                __half2 mB = __floats2half2_rn(cm[2], cm[3]);
                uint2 pw, pm;
                pw.x = *(unsigned*)&wA; pw.y = *(unsigned*)&wB;
                pm.x = *(unsigned*)&mA; pm.y = *(unsigned*)&mB;
                *(uint2*)(g_IWh + row * 128 + (tx << 2)) = pw;
                *(uint2*)(g_IMh + row * 128 + (tx << 2)) = pm;
            }
        }
    }
}

// ============================================================================
// Kernel B: per_graph gather-sum + softmax -> E.  fp16 gathers, fp32 accumulate.
// ============================================================================
__global__ void __launch_bounds__(256) kB(const int* __restrict__ node_type,
                                          const int* __restrict__ nbr_type) {
    __shared__ int   sNT[64];
    __shared__ int   sNB[512];
    __shared__ float sP[8][132];
    __shared__ float sredm[8];
    __shared__ float sreds[8];

    const int tid = threadIdx.x;
    const int g = blockIdx.x;
    const int w = tid >> 5, lane = tid & 31;

    if (tid < 64) sNT[tid] = node_type[g * 64 + tid];
    for (int idx = tid; idx < 512; idx += 256) sNB[idx] = nbr_type[g * 512 + idx];
    __syncthreads();

    const int co = lane << 2;
    float4 acc = make_float4(0.f, 0.f, 0.f, 0.f);
#pragma unroll 2
    for (int kk = 0; kk < 8; ++kk) {
        const int k = (kk << 3) + w;
        float4 s = ldh4(g_IWh + (size_t)sNT[k] * 128 + co);
        const int* nbp = &sNB[k << 3];
#pragma unroll
        for (int d = 0; d < 8; ++d) {
            const float4 v = ldh4(g_IMh + (size_t)nbp[d] * 128 + co);
            s.x += v.x; s.y += v.y; s.z += v.z; s.w += v.w;
        }
        acc.x += fmaxf(s.x, 0.f);
        acc.y += fmaxf(s.y, 0.f);
        acc.z += fmaxf(s.z, 0.f);
        acc.w += fmaxf(s.w, 0.f);
    }
    *(float4*)(&sP[w][co]) = acc;
    __syncthreads();

    float v = 0.f;
    if (tid < 128) {
#pragma unroll
        for (int ww = 0; ww < 8; ++ww) v += sP[ww][tid];
    }
    float m = v;
#pragma unroll
    for (int off = 16; off; off >>= 1)
        m = fmaxf(m, __shfl_xor_sync(0xffffffffu, m, off));
    if (lane == 0) sredm[w] = m;
    __syncthreads();
    const float M = fmaxf(fmaxf(sredm[0], sredm[1]), fmaxf(sredm[2], sredm[3]));

    const float e = (tid < 128) ? expf(v - M) : 0.f;
    float s = e;
#pragma unroll
    for (int off = 16; off; off >>= 1)
        s += __shfl_xor_sync(0xffffffffu, s, off);
    if (lane == 0) sreds[w] = s;
    __syncthreads();
    const float tot = sreds[0] + sreds[1] + sreds[2] + sreds[3];

    if (tid < 128) g_E[g * 128 + tid] = e / tot;
}

// ============================================================================
// Kernel C: ext = E @ U.T + Esum @ V.T ;  X = softmax(relu(ext))  (f32x2 math)
// ============================================================================
#define C_WSTR 132
#define C_ASTR 36
#define SMEM_C ((2 * 128 * C_WSTR + 2 * 128 * C_ASTR) * 4 + 512 * 4)

__global__ void __launch_bounds__(256) kC(const float* __restrict__ U,
                                          const float* __restrict__ V,
                                          const int* __restrict__ ext_nbr) {
    extern __shared__ float sm[];
    float* sUt = sm;
    float* sVt = sUt + 128 * C_WSTR;
    float* sEt = sVt + 128 * C_WSTR;     // [128][C_ASTR] transposed E tile
    float* sSt = sEt + 128 * C_ASTR;     // [128][C_ASTR] transposed Esum tile
    int*   sXN = (int*)(sSt + 128 * C_ASTR);  // [32*16]

    const int tid = threadIdx.x;
    const int rowBase = blockIdx.x * 32;

    for (int idx = tid; idx < 128 * 128; idx += 256) {
        int j = idx >> 7, i = idx & 127;
        sUt[i * C_WSTR + j] = U[idx];
        sVt[i * C_WSTR + j] = V[idx];
    }
    for (int idx = tid; idx < 32 * 128; idx += 256) {
        int r = idx >> 7, i = idx & 127;
        int row = rowBase + r;
        sEt[i * C_ASTR + r] = (row < NG) ? g_E[row * 128 + i] : 0.f;
    }
    for (int idx = tid; idx < 512; idx += 256) {
        int row = rowBase + (idx >> 4);
        sXN[idx] = (row < NG) ? ext_nbr[row * 16 + (idx & 15)] : 0;
    }
    __syncthreads();

    // Esum tile: vectorized float4 gather of 16 E rows per graph
    for (int idx = tid; idx < 32 * 32; idx += 256) {
        int r = idx >> 5, c4 = (idx & 31) << 2;
        const int* xn = &sXN[r * 16];
        float4 s = make_float4(0.f, 0.f, 0.f, 0.f);
#pragma unroll
        for (int d = 0; d < 16; ++d) {
            const float4 v = *(const float4*)(g_E + xn[d] * 128 + c4);
            s.x += v.x; s.y += v.y; s.z += v.z; s.w += v.w;
        }
        sSt[(c4 + 0) * C_ASTR + r] = s.x;
        sSt[(c4 + 1) * C_ASTR + r] = s.y;
        sSt[(c4 + 2) * C_ASTR + r] = s.z;
        sSt[(c4 + 3) * C_ASTR + r] = s.w;
    }
    __syncthreads();

    const int tx = tid & 31;  // 4 cols
    const int ty = tid >> 5;  // 4 rows
    u64t acc2[2][4] = {};     // [rr-pair][cc]

#pragma unroll 4
    for (int i = 0; i < 128; ++i) {
        const float4 uv = *(const float4*)(sUt + i * C_WSTR + (tx << 2));
        const float4 vv = *(const float4*)(sVt + i * C_WSTR + (tx << 2));
        const float4 ev = *(const float4*)(sEt + i * C_ASTR + (ty << 2));
        const float4 qv = *(const float4*)(sSt + i * C_ASTR + (ty << 2));
        u64t ep[2], sp[2], ud[4], vd[4];
        ep[0] = pk2(ev.x, ev.y); ep[1] = pk2(ev.z, ev.w);
        sp[0] = pk2(qv.x, qv.y); sp[1] = pk2(qv.z, qv.w);
        ud[0] = pk2(uv.x, uv.x); ud[1] = pk2(uv.y, uv.y);
        ud[2] = pk2(uv.z, uv.z); ud[3] = pk2(uv.w, uv.w);
        vd[0] = pk2(vv.x, vv.x); vd[1] = pk2(vv.y, vv.y);
        vd[2] = pk2(vv.z, vv.z); vd[3] = pk2(vv.w, vv.w);
#pragma unroll
        for (int rp = 0; rp < 2; ++rp) {
#pragma unroll
            for (int cc = 0; cc < 4; ++cc) {
                FMA2(acc2[rp][cc], ep[rp], ud[cc]);
                FMA2(acc2[rp][cc], sp[rp], vd[cc]);
            }
        }
    }

#pragma unroll
    for (int rp = 0; rp < 2; ++rp) {
        const float2 c0 = upk2(acc2[rp][0]);
        const float2 c1 = upk2(acc2[rp][1]);
        const float2 c2 = upk2(acc2[rp][2]);
        const float2 c3 = upk2(acc2[rp][3]);
#pragma unroll
        for (int h = 0; h < 2; ++h) {
            const int row = rowBase + (ty << 2) + (rp << 1) + h;
            float v0 = fmaxf(h ? c0.y : c0.x, 0.f);
            float v1 = fmaxf(h ? c1.y : c1.x, 0.f);
            float v2 = fmaxf(h ? c2.y : c2.x, 0.f);
            float v3 = fmaxf(h ? c3.y : c3.x, 0.f);
            float m = fmaxf(fmaxf(v0, v1), fmaxf(v2, v3));
#pragma unroll
            for (int off = 16; off; off >>= 1)
                m = fmaxf(m, __shfl_xor_sync(0xffffffffu, m, off));
            float e0 = expf(v0 - m), e1 = expf(v1 - m), e2 = expf(v2 - m), e3 = expf(v3 - m);
            float s = e0 + e1 + e2 + e3;
#pragma unroll
            for (int off = 16; off; off >>= 1)
                s += __shfl_xor_sync(0xffffffffu, s, off);
            if (row < NG) {
                const float inv = 1.f / s;
                float4 o = make_float4(e0 * inv, e1 * inv, e2 * inv, e3 * inv);
                *(float4*)(g_X + row * 128 + (tx << 2)) = o;
            }
        }
    }
}

// ============================================================================
// Kernel D (single pass, fp16 W1): 128 blocks x 8 rows; 256 threads.
// sWh [128][264] halves -> conflict-free LDS.128 of 8 halves.
// ============================================================================
#define D2_STR 264
#define SMEM_D (128 * D2_STR * 2)

__global__ void __launch_bounds__(256) kD(const int* __restrict__ batch,
                                          const float* __restrict__ b1,
                                          const float* __restrict__ W2,
                                          const float* __restrict__ b2,
                                          float* __restrict__ out) {
    extern __shared__ __half sWh[];      // [128][D2_STR]
    __shared__ float sF[8][260];         // feat per row (16B-aligned stride)
    __shared__ float sW2[256];
    __shared__ float sB1[128];
    __shared__ float sP[8][4][2];        // [warp][row-in-group][logit]

    const int tid = threadIdx.x;
    const int rg = tid >> 7;             // 0/1 -> rows rg*4 .. rg*4+3
    const int j = tid & 127;
    const int warp = tid >> 5, lane = tid & 31;

    // W1h fill: 4096 uint4 (8 halves each), conflict-free STS.128
    for (int q = tid; q < 128 * 32; q += 256) {
        const uint4 v = *(const uint4*)(g_W1h + (q << 3));
        const int jr = q >> 5, i8 = (q & 31) << 3;
        *(uint4*)(sWh + jr * D2_STR + i8) = v;
    }
    sW2[tid] = W2[tid];
    if (tid < 128) sB1[tid] = b1[tid];
    const float bb0 = b2[0], bb1 = b2[1];

    for (int rr = rg; rr < 8; rr += 2) {
        const int row = blockIdx.x * 8 + rr;
        const int b0i = batch[2 * row];
        const int b1i = batch[2 * row + 1];
        const float e1 = g_X[b0i * 128 + j];
        const float e2 = g_X[b1i * 128 + j];
        sF[rr][j] = e1 * e2;
        sF[rr][128 + j] = e1 + e2;
    }
    __syncthreads();

    float4 a0 = make_float4(0.f, 0.f, 0.f, 0.f);
    float4 a1 = a0, a2 = a0, a3 = a0;
    const __half* wrow = sWh + j * D2_STR;
    const int rb = rg << 2;
#pragma unroll 4
    for (int m = 0; m < 32; ++m) {
        const uint4 wv = *(const uint4*)(wrow + (m << 3));
        const float2 w01 = __half22float2(*(const __half2*)&wv.x);
        const float2 w23 = __half22float2(*(const __half2*)&wv.y);
        const float2 w45 = __half22float2(*(const __half2*)&wv.z);
        const float2 w67 = __half22float2(*(const __half2*)&wv.w);
        const float4 f0a = *(const float4*)(&sF[rb + 0][m << 3]);
        const float4 f0b = *(const float4*)(&sF[rb + 0][(m << 3) + 4]);
        const float4 f1a = *(const float4*)(&sF[rb + 1][m << 3]);
        const float4 f1b = *(const float4*)(&sF[rb + 1][(m << 3) + 4]);
        const float4 f2a = *(const float4*)(&sF[rb + 2][m << 3]);
        const float4 f2b = *(const float4*)(&sF[rb + 2][(m << 3) + 4]);
        const float4 f3a = *(const float4*)(&sF[rb + 3][m << 3]);
        const float4 f3b = *(const float4*)(&sF[rb + 3][(m << 3) + 4]);
        a0.x = fmaf(f0a.x, w01.x, a0.x); a0.y = fmaf(f0a.y, w01.y, a0.y);
        a0.z = fmaf(f0a.z, w23.x, a0.z); a0.w = fmaf(f0a.w, w23.y, a0.w);
        a0.x = fmaf(f0b.x, w45.x, a0.x); a0.y = fmaf(f0b.y, w45.y, a0.y);
        a0.z = fmaf(f0b.z, w67.x, a0.z); a0.w = fmaf(f0b.w, w67.y, a0.w);
        a1.x = fmaf(f1a.x, w01.x, a1.x); a1.y = fmaf(f1a.y, w01.y, a1.y);
        a1.z = fmaf(f1a.z, w23.x, a1.z); a1.w = fmaf(f1a.w, w23.y, a1.w);
        a1.x = fmaf(f1b.x, w45.x, a1.x); a1.y = fmaf(f1b.y, w45.y, a1.y);
        a1.z = fmaf(f1b.z, w67.x, a1.z); a1.w = fmaf(f1b.w, w67.y, a1.w);
        a2.x = fmaf(f2a.x, w01.x, a2.x); a2.y = fmaf(f2a.y, w01.y, a2.y);
        a2.z = fmaf(f2a.z, w23.x, a2.z); a2.w = fmaf(f2a.w, w23.y, a2.w);
        a2.x = fmaf(f2b.x, w45.x, a2.x); a2.y = fmaf(f2b.y, w45.y, a2.y);
        a2.z = fmaf(f2b.z, w67.x, a2.z); a2.w = fmaf(f2b.w, w67.y, a2.w);
        a3.x = fmaf(f3a.x, w01.x, a3.x); a3.y = fmaf(f3a.y, w01.y, a3.y);
        a3.z = fmaf(f3a.z, w23.x, a3.z); a3.w = fmaf(f3a.w, w23.y, a3.w);
        a3.x = fmaf(f3b.x, w45.x, a3.x); a3.y = fmaf(f3b.y, w45.y, a3.y);
        a3.z = fmaf(f3b.z, w67.x, a3.z); a3.w = fmaf(f3b.w, w67.y, a3.w);
    }

    const float bj = sB1[j];
    const float w2a = sW2[j], w2b = sW2[128 + j];
    float h0 = fmaxf((a0.x + a0.y) + (a0.z + a0.w) + bj, 0.f);
    float h1 = fmaxf((a1.x + a1.y) + (a1.z + a1.w) + bj, 0.f);
    float h2 = fmaxf((a2.x + a2.y) + (a2.z + a2.w) + bj, 0.f);
    float h3 = fmaxf((a3.x + a3.y) + (a3.z + a3.w) + bj, 0.f);

    float p00 = h0 * w2a, p01 = h0 * w2b;
    float p10 = h1 * w2a, p11 = h1 * w2b;
    float p20 = h2 * w2a, p21 = h2 * w2b;
    float p30 = h3 * w2a, p31 = h3 * w2b;
#pragma unroll
    for (int off = 16; off; off >>= 1) {
        p00 += __shfl_xor_sync(0xffffffffu, p00, off);
        p01 += __shfl_xor_sync(0xffffffffu, p01, off);
        p10 += __shfl_xor_sync(0xffffffffu, p10, off);
        p11 += __shfl_xor_sync(0xffffffffu, p11, off);
        p20 += __shfl_xor_sync(0xffffffffu, p20, off);
        p21 += __shfl_xor_sync(0xffffffffu, p21, off);
        p30 += __shfl_xor_sync(0xffffffffu, p30, off);
        p31 += __shfl_xor_sync(0xffffffffu, p31, off);
    }
    if (lane == 0) {
        sP[warp][0][0] = p00; sP[warp][0][1] = p01;
        sP[warp][1][0] = p10; sP[warp][1][1] = p11;
        sP[warp][2][0] = p20; sP[warp][2][1] = p21;
        sP[warp][3][0] = p30; sP[warp][3][1] = p31;
    }
    __syncthreads();

    if (tid < 8) {
        const int trg = tid >> 2, r = tid & 3;
        const int row = blockIdx.x * 8 + trg * 4 + r;
        float o0 = bb0, o1 = bb1;
#pragma unroll
        for (int w2 = 0; w2 < 4; ++w2) {
            o0 += sP[trg * 4 + w2][r][0];
            o1 += sP[trg * 4 + w2][r][1];
        }
        const float mm = fmaxf(o0, o1);
        const float z0 = expf(o0 - mm), z1 = expf(o1 - mm);
        const float inv = 1.f / (z0 + z1);
        out[row * 2]     = z0 * inv;
        out[row * 2 + 1] = z1 * inv;
    }
}

// ============================================================================
extern "C" void kernel_launch(void* const* d_in, const int* in_sizes, int n_in,
                              void* d_out, int out_size) {
    const int*   batch     = (const int*)d_in[0];
    const int*   node_type = (const int*)d_in[1];
    const int*   nbr_type  = (const int*)d_in[2];
    const int*   ext_nbr   = (const int*)d_in[3];
    const float* impact    = (const float*)d_in[4];
    const float* W         = (const float*)d_in[5];
    const float* M         = (const float*)d_in[6];
    const float* U         = (const float*)d_in[7];
    const float* V         = (const float*)d_in[8];
    const float* W1        = (const float*)d_in[9];
    const float* b1        = (const float*)d_in[10];
    const float* W2        = (const float*)d_in[11];
    const float* b2        = (const float*)d_in[12];
    float* out = (float*)d_out;

    cudaFuncSetAttribute(kA, cudaFuncAttributeMaxDynamicSharedMemorySize, SMEM_A);
    cudaFuncSetAttribute(kC, cudaFuncAttributeMaxDynamicSharedMemorySize, SMEM_C);
    cudaFuncSetAttribute(kD, cudaFuncAttributeMaxDynamicSharedMemorySize, SMEM_D);

    kA<<<(NTYPES + 63) / 64, 256, SMEM_A>>>(impact, W, M, W1);
    kB<<<NG, 256>>>(node_type, nbr_type);
    kC<<<(NG + 31) / 32, 256, SMEM_C>>>(U, V, ext_nbr);
    kD<<<NB / 8, 256, SMEM_D>>>(batch, b1, W2, b2, out);
}

// round 5
// speedup vs baseline: 1.0509x; 1.0509x over previous
#include <cuda_runtime.h>
#include <cuda_fp16.h>
#include <math.h>

#define NTYPES 10000
#define NG     2000
#define NB     1024

// ---------------- scratch (device globals; no allocation allowed) ----------------
__device__ unsigned char g_IW8[NTYPES * 128];  // impact @ W.T  (e4m3)
__device__ unsigned char g_IM8[NTYPES * 128];  // impact @ M.T  (e4m3)
__device__ __half g_W1h[128 * 256];            // W1 in fp16
__device__ float  g_E [NG * 128];              // softmax(per_graph)
__device__ float  g_X [NG * 128];              // softmax(relu(ext))

// ---- packed f32x2 ----
typedef unsigned long long u64t;
__device__ __forceinline__ u64t pk2(float lo, float hi) {
    u64t r;
    asm("mov.b64 %0, {%1, %2};" : "=l"(r) : "r"(__float_as_uint(lo)), "r"(__float_as_uint(hi)));
    return r;
}
__device__ __forceinline__ float2 upk2(u64t v) {
    unsigned lo, hi;
    asm("mov.b64 {%0, %1}, %2;" : "=r"(lo), "=r"(hi) : "l"(v));
    return make_float2(__uint_as_float(lo), __uint_as_float(hi));
}
#define FMA2(d, a, b) asm("fma.rn.f32x2 %0, %1, %2, %0;" : "+l"(d) : "l"(a), "l"(b))

// ---- fp8 e4m3 pack/unpack ----
__device__ __forceinline__ unsigned short f2_to_e4m3x2(float lo, float hi) {
    unsigned short r;
    asm("cvt.rn.satfinite.e4m3x2.f32 %0, %1, %2;" : "=h"(r) : "f"(hi), "f"(lo));
    return r;  // low byte <- lo
}
__device__ __forceinline__ __half2 e4m3x2_to_h2(unsigned short u) {
    unsigned h;
    asm("cvt.rn.f16x2.e4m3x2 %0, %1;" : "=r"(h) : "h"(u));
    return *(__half2*)&h;  // .x <- low byte
}

// ============================================================================
// Kernel A: IW = impact @ W.T, IM = impact @ M.T  -> fp8 tables (f32x2 math)
// Blocks 0..15 additionally convert W1 -> g_W1h (fp16).
// ============================================================================
#define A_WSTR 132
#define A_ASTR 68
#define SMEM_A ((2 * 128 * A_WSTR + 128 * A_ASTR) * 4)

__global__ void __launch_bounds__(256) kA(const float* __restrict__ impact,
                                          const float* __restrict__ W,
                                          const float* __restrict__ M,
                                          const float* __restrict__ W1) {
    extern __shared__ float sm[];
    float* sWt = sm;                       // [128][A_WSTR]  Wt[i][j] = W[j][i]
    float* sMt = sm + 128 * A_WSTR;
    float* sAt = sm + 2 * 128 * A_WSTR;    // [128][A_ASTR]  At[i][r]

    const int tid = threadIdx.x;
    const int rowBase = blockIdx.x * 64;

    if (blockIdx.x < 16) {
        const int base = blockIdx.x * 2048;
        for (int q = tid; q < 1024; q += 256) {
            const float2 v = *(const float2*)(W1 + base + (q << 1));
            *(__half2*)(g_W1h + base + (q << 1)) = __floats2half2_rn(v.x, v.y);
        }
    }

    for (int idx = tid; idx < 128 * 128; idx += 256) {
        int j = idx >> 7, i = idx & 127;
        sWt[i * A_WSTR + j] = W[idx];
        sMt[i * A_WSTR + j] = M[idx];
    }
    for (int idx = tid; idx < 64 * 128; idx += 256) {
        int r = idx >> 7, i = idx & 127;
        int row = rowBase + r;
        sAt[i * A_ASTR + r] = (row < NTYPES) ? impact[row * 128 + i] : 0.f;
    }
    __syncthreads();

    const int tx = tid & 31;   // 4-col group
    const int ty = tid >> 5;   // 8-row group
    u64t accW2[4][4] = {};
    u64t accM2[4][4] = {};

#pragma unroll 4
    for (int i = 0; i < 128; ++i) {
        const float4 wv = *(const float4*)(sWt + i * A_WSTR + (tx << 2));
        const float4 mv = *(const float4*)(sMt + i * A_WSTR + (tx << 2));
        const float4 a0 = *(const float4*)(sAt + i * A_ASTR + (ty << 3));
        const float4 a1 = *(const float4*)(sAt + i * A_ASTR + (ty << 3) + 4);
        u64t ap[4], wd[4], md[4];
        ap[0] = pk2(a0.x, a0.y); ap[1] = pk2(a0.z, a0.w);
        ap[2] = pk2(a1.x, a1.y); ap[3] = pk2(a1.z, a1.w);
        wd[0] = pk2(wv.x, wv.x); wd[1] = pk2(wv.y, wv.y);
        wd[2] = pk2(wv.z, wv.z); wd[3] = pk2(wv.w, wv.w);
        md[0] = pk2(mv.x, mv.x); md[1] = pk2(mv.y, mv.y);
        md[2] = pk2(mv.z, mv.z); md[3] = pk2(mv.w, mv.w);
#pragma unroll
        for (int rp = 0; rp < 4; ++rp) {
#pragma unroll
            for (int cc = 0; cc < 4; ++cc) {
                FMA2(accW2[rp][cc], ap[rp], wd[cc]);
                FMA2(accM2[rp][cc], ap[rp], md[cc]);
            }
        }
    }

#pragma unroll
    for (int rp = 0; rp < 4; ++rp) {
        float2 w0 = upk2(accW2[rp][0]), w1 = upk2(accW2[rp][1]);
        float2 w2 = upk2(accW2[rp][2]), w3 = upk2(accW2[rp][3]);
        float2 m0 = upk2(accM2[rp][0]), m1 = upk2(accM2[rp][1]);
        float2 m2 = upk2(accM2[rp][2]), m3 = upk2(accM2[rp][3]);
#pragma unroll
        for (int h = 0; h < 2; ++h) {
            const int row = rowBase + (ty << 3) + (rp << 1) + h;
            if (row < NTYPES) {
                const float cw0 = h ? w0.y : w0.x, cw1 = h ? w1.y : w1.x;
                const float cw2 = h ? w2.y : w2.x, cw3 = h ? w3.y : w3.x;
                const float cm0 = h ? m0.y : m0.x, cm1 = h ? m1.y : m1.x;
                const float cm2 = h ? m2.y : m2.x, cm3 = h ? m3.y : m3.x;
                const unsigned pw = (unsigned)f2_to_e4m3x2(cw0, cw1)
                                  | ((unsigned)f2_to_e4m3x2(cw2, cw3) << 16);
                const unsigned pm = (unsigned)f2_to_e4m3x2(cm0, cm1)
                                  | ((unsigned)f2_to_e4m3x2(cm2, cm3) << 16);
                *(unsigned*)(g_IW8 + row * 128 + (tx << 2)) = pw;
                *(unsigned*)(g_IM8 + row * 128 + (tx << 2)) = pm;
            }
        }
    }
}

// ============================================================================
// Kernel B: per_graph gather-sum + softmax -> E.
// fp8 gathers (LDG.32 = 4 cols/lane), half2 inner accumulate, fp32 outer.
// ============================================================================
__global__ void __launch_bounds__(256) kB(const int* __restrict__ node_type,
                                          const int* __restrict__ nbr_type) {
    __shared__ int   sNT[64];
    __shared__ int   sNB[512];
    __shared__ float sP[8][132];
    __shared__ float sredm[8];
    __shared__ float sreds[8];

    const int tid = threadIdx.x;
    const int g = blockIdx.x;
    const int w = tid >> 5, lane = tid & 31;

    if (tid < 64) sNT[tid] = node_type[g * 64 + tid];
    for (int idx = tid; idx < 512; idx += 256) sNB[idx] = nbr_type[g * 512 + idx];
    __syncthreads();

    const int co = lane << 2;     // 4 fp8 columns per lane
    float4 acc = make_float4(0.f, 0.f, 0.f, 0.f);
#pragma unroll 2
    for (int kk = 0; kk < 8; ++kk) {
        const int k = (kk << 3) + w;
        unsigned u = *(const unsigned*)(g_IW8 + (size_t)sNT[k] * 128 + co);
        __half2 s01 = e4m3x2_to_h2((unsigned short)(u & 0xFFFF));
        __half2 s23 = e4m3x2_to_h2((unsigned short)(u >> 16));
        const int* nbp = &sNB[k << 3];
#pragma unroll
        for (int d = 0; d < 8; ++d) {
            const unsigned v = *(const unsigned*)(g_IM8 + (size_t)nbp[d] * 128 + co);
            s01 = __hadd2(s01, e4m3x2_to_h2((unsigned short)(v & 0xFFFF)));
            s23 = __hadd2(s23, e4m3x2_to_h2((unsigned short)(v >> 16)));
        }
        const float2 f01 = __half22float2(s01);
        const float2 f23 = __half22float2(s23);
        acc.x += fmaxf(f01.x, 0.f);
        acc.y += fmaxf(f01.y, 0.f);
        acc.z += fmaxf(f23.x, 0.f);
        acc.w += fmaxf(f23.y, 0.f);
    }
    *(float4*)(&sP[w][co]) = acc;
    __syncthreads();

    float v = 0.f;
    if (tid < 128) {
#pragma unroll
        for (int ww = 0; ww < 8; ++ww) v += sP[ww][tid];
    }
    float m = v;
#pragma unroll
    for (int off = 16; off; off >>= 1)
        m = fmaxf(m, __shfl_xor_sync(0xffffffffu, m, off));
    if (lane == 0) sredm[w] = m;
    __syncthreads();
    const float M = fmaxf(fmaxf(sredm[0], sredm[1]), fmaxf(sredm[2], sredm[3]));

    const float e = (tid < 128) ? expf(v - M) : 0.f;
    float s = e;
#pragma unroll
    for (int off = 16; off; off >>= 1)
        s += __shfl_xor_sync(0xffffffffu, s, off);
    if (lane == 0) sreds[w] = s;
    __syncthreads();
    const float tot = sreds[0] + sreds[1] + sreds[2] + sreds[3];

    if (tid < 128) g_E[g * 128 + tid] = e / tot;
}

// ============================================================================
// Kernel C: ext = E @ U.T + Esum @ V.T ;  X = softmax(relu(ext))  (f32x2)
// ============================================================================
#define C_WSTR 132
#define C_ASTR 36
#define SMEM_C ((2 * 128 * C_WSTR + 2 * 128 * C_ASTR) * 4 + 512 * 4)

__global__ void __launch_bounds__(256) kC(const float* __restrict__ U,
                                          const float* __restrict__ V,
                                          const int* __restrict__ ext_nbr) {
    extern __shared__ float sm[];
    float* sUt = sm;
    float* sVt = sUt + 128 * C_WSTR;
    float* sEt = sVt + 128 * C_WSTR;     // [128][C_ASTR] transposed E tile
    float* sSt = sEt + 128 * C_ASTR;     // [128][C_ASTR] transposed Esum tile
    int*   sXN = (int*)(sSt + 128 * C_ASTR);  // [32*16]

    const int tid = threadIdx.x;
    const int rowBase = blockIdx.x * 32;

    for (int idx = tid; idx < 128 * 128; idx += 256) {
        int j = idx >> 7, i = idx & 127;
        sUt[i * C_WSTR + j] = U[idx];
        sVt[i * C_WSTR + j] = V[idx];
    }
    for (int idx = tid; idx < 32 * 128; idx += 256) {
        int r = idx >> 7, i = idx & 127;
        int row = rowBase + r;
        sEt[i * C_ASTR + r] = (row < NG) ? g_E[row * 128 + i] : 0.f;
    }
    for (int idx = tid; idx < 512; idx += 256) {
        int row = rowBase + (idx >> 4);
        sXN[idx] = (row < NG) ? ext_nbr[row * 16 + (idx & 15)] : 0;
    }
    __syncthreads();

    for (int idx = tid; idx < 32 * 32; idx += 256) {
        int r = idx >> 5, c4 = (idx & 31) << 2;
        const int* xn = &sXN[r * 16];
        float4 s = make_float4(0.f, 0.f, 0.f, 0.f);
#pragma unroll
        for (int d = 0; d < 16; ++d) {
            const float4 v = *(const float4*)(g_E + xn[d] * 128 + c4);
            s.x += v.x; s.y += v.y; s.z += v.z; s.w += v.w;
        }
        sSt[(c4 + 0) * C_ASTR + r] = s.x;
        sSt[(c4 + 1) * C_ASTR + r] = s.y;
        sSt[(c4 + 2) * C_ASTR + r] = s.z;
        sSt[(c4 + 3) * C_ASTR + r] = s.w;
    }
    __syncthreads();

    const int tx = tid & 31;  // 4 cols
    const int ty = tid >> 5;  // 4 rows
    u64t acc2[2][4] = {};

#pragma unroll 4
    for (int i = 0; i < 128; ++i) {
        const float4 uv = *(const float4*)(sUt + i * C_WSTR + (tx << 2));
        const float4 vv = *(const float4*)(sVt + i * C_WSTR + (tx << 2));
        const float4 ev = *(const float4*)(sEt + i * C_ASTR + (ty << 2));
        const float4 qv = *(const float4*)(sSt + i * C_ASTR + (ty << 2));
        u64t ep[2], sp[2], ud[4], vd[4];
        ep[0] = pk2(ev.x, ev.y); ep[1] = pk2(ev.z, ev.w);
        sp[0] = pk2(qv.x, qv.y); sp[1] = pk2(qv.z, qv.w);
        ud[0] = pk2(uv.x, uv.x); ud[1] = pk2(uv.y, uv.y);
        ud[2] = pk2(uv.z, uv.z); ud[3] = pk2(uv.w, uv.w);
        vd[0] = pk2(vv.x, vv.x); vd[1] = pk2(vv.y, vv.y);
        vd[2] = pk2(vv.z, vv.z); vd[3] = pk2(vv.w, vv.w);
#pragma unroll
        for (int rp = 0; rp < 2; ++rp) {
#pragma unroll
            for (int cc = 0; cc < 4; ++cc) {
                FMA2(acc2[rp][cc], ep[rp], ud[cc]);
                FMA2(acc2[rp][cc], sp[rp], vd[cc]);
            }
        }
    }

#pragma unroll
    for (int rp = 0; rp < 2; ++rp) {
        const float2 c0 = upk2(acc2[rp][0]);
        const float2 c1 = upk2(acc2[rp][1]);
        const float2 c2 = upk2(acc2[rp][2]);
        const float2 c3 = upk2(acc2[rp][3]);
#pragma unroll
        for (int h = 0; h < 2; ++h) {
            const int row = rowBase + (ty << 2) + (rp << 1) + h;
            float v0 = fmaxf(h ? c0.y : c0.x, 0.f);
            float v1 = fmaxf(h ? c1.y : c1.x, 0.f);
            float v2 = fmaxf(h ? c2.y : c2.x, 0.f);
            float v3 = fmaxf(h ? c3.y : c3.x, 0.f);
            float m = fmaxf(fmaxf(v0, v1), fmaxf(v2, v3));
#pragma unroll
            for (int off = 16; off; off >>= 1)
                m = fmaxf(m, __shfl_xor_sync(0xffffffffu, m, off));
            float e0 = expf(v0 - m), e1 = expf(v1 - m), e2 = expf(v2 - m), e3 = expf(v3 - m);
            float s = e0 + e1 + e2 + e3;
#pragma unroll
            for (int off = 16; off; off >>= 1)
                s += __shfl_xor_sync(0xffffffffu, s, off);
            if (row < NG) {
                const float inv = 1.f / s;
                float4 o = make_float4(e0 * inv, e1 * inv, e2 * inv, e3 * inv);
                *(float4*)(g_X + row * 128 + (tx << 2)) = o;
            }
        }
    }
}

// ============================================================================
// Kernel D: 256 blocks x 4 rows; 256 threads; fp16 W1 (67KB smem -> 2-3
// blocks co-resident per SM so weight fill overlaps neighbor compute).
// Thread (rg = tid>>7, j = tid&127) handles rows rg*2, rg*2+1.
// ============================================================================
#define D2_STR 264
#define SMEM_D (128 * D2_STR * 2)

__global__ void __launch_bounds__(256) kD(const int* __restrict__ batch,
                                          const float* __restrict__ b1,
                                          const float* __restrict__ W2,
                                          const float* __restrict__ b2,
                                          float* __restrict__ out) {
    extern __shared__ __half sWh[];      // [128][D2_STR]
    __shared__ float sF[4][260];
    __shared__ float sW2[256];
    __shared__ float sB1[128];
    __shared__ float sP[8][2][2];        // [warp][local-row][logit]

    const int tid = threadIdx.x;
    const int rg = tid >> 7;             // 0/1 -> local rows rg*2, rg*2+1
    const int j = tid & 127;
    const int warp = tid >> 5, lane = tid & 31;

    for (int q = tid; q < 128 * 32; q += 256) {
        const uint4 v = *(const uint4*)(g_W1h + (q << 3));
        const int jr = q >> 5, i8 = (q & 31) << 3;
        *(uint4*)(sWh + jr * D2_STR + i8) = v;
    }
    sW2[tid] = W2[tid];
    if (tid < 128) sB1[tid] = b1[tid];
    const float bb0 = b2[0], bb1 = b2[1];

    const int rb = rg << 1;
#pragma unroll
    for (int rr = 0; rr < 2; ++rr) {
        const int row = blockIdx.x * 4 + rb + rr;
        const int b0i = batch[2 * row];
        const int b1i = batch[2 * row + 1];
        const float e1 = g_X[b0i * 128 + j];
        const float e2 = g_X[b1i * 128 + j];
        sF[rb + rr][j] = e1 * e2;
        sF[rb + rr][128 + j] = e1 + e2;
    }
    __syncthreads();

    float4 a0 = make_float4(0.f, 0.f, 0.f, 0.f);
    float4 a1 = a0;
    const __half* wrow = sWh + j * D2_STR;
#pragma unroll 4
    for (int m = 0; m < 32; ++m) {
        const uint4 wv = *(const uint4*)(wrow + (m << 3));
        const float2 w01 = __half22float2(*(const __half2*)&wv.x);
        const float2 w23 = __half22float2(*(const __half2*)&wv.y);
        const float2 w45 = __half22float2(*(const __half2*)&wv.z);
        const float2 w67 = __half22float2(*(const __half2*)&wv.w);
        const float4 f0a = *(const float4*)(&sF[rb + 0][m << 3]);
        const float4 f0b = *(const float4*)(&sF[rb + 0][(m << 3) + 4]);
        const float4 f1a = *(const float4*)(&sF[rb + 1][m << 3]);
        const float4 f1b = *(const float4*)(&sF[rb + 1][(m << 3) + 4]);
        a0.x = fmaf(f0a.x, w01.x, a0.x); a0.y = fmaf(f0a.y, w01.y, a0.y);
        a0.z = fmaf(f0a.z, w23.x, a0.z); a0.w = fmaf(f0a.w, w23.y, a0.w);
        a0.x = fmaf(f0b.x, w45.x, a0.x); a0.y = fmaf(f0b.y, w45.y, a0.y);
        a0.z = fmaf(f0b.z, w67.x, a0.z); a0.w = fmaf(f0b.w, w67.y, a0.w);
        a1.x = fmaf(f1a.x, w01.x, a1.x); a1.y = fmaf(f1a.y, w01.y, a1.y);
        a1.z = fmaf(f1a.z, w23.x, a1.z); a1.w = fmaf(f1a.w, w23.y, a1.w);
        a1.x = fmaf(f1b.x, w45.x, a1.x); a1.y = fmaf(f1b.y, w45.y, a1.y);
        a1.z = fmaf(f1b.z, w67.x, a1.z); a1.w = fmaf(f1b.w, w67.y, a1.w);
    }

    const float bj = sB1[j];
    const float w2a = sW2[j], w2b = sW2[128 + j];
    const float h0 = fmaxf((a0.x + a0.y) + (a0.z + a0.w) + bj, 0.f);
    const float h1 = fmaxf((a1.x + a1.y) + (a1.z + a1.w) + bj, 0.f);

    float p00 = h0 * w2a, p01 = h0 * w2b;
    float p10 = h1 * w2a, p11 = h1 * w2b;
#pragma unroll
    for (int off = 16; off; off >>= 1) {
        p00 += __shfl_xor_sync(0xffffffffu, p00, off);
        p01 += __shfl_xor_sync(0xffffffffu, p01, off);
        p10 += __shfl_xor_sync(0xffffffffu, p10, off);
        p11 += __shfl_xor_sync(0xffffffffu, p11, off);
    }
    if (lane == 0) {
        sP[warp][0][0] = p00; sP[warp][0][1] = p01;
        sP[warp][1][0] = p10; sP[warp][1][1] = p11;
    }
    __syncthreads();

    if (tid < 4) {
        const int r = tid;                    // local row 0..3
        const int wbase = (r >> 1) << 2;      // warps 0-3 hold rows 0,1; 4-7 hold 2,3
        const int lr = r & 1;
        const int row = blockIdx.x * 4 + r;
        float o0 = bb0, o1 = bb1;
#pragma unroll
        for (int w2 = 0; w2 < 4; ++w2) {
            o0 += sP[wbase + w2][lr][0];
            o1 += sP[wbase + w2][lr][1];
        }
        const float mm = fmaxf(o0, o1);
        const float z0 = expf(o0 - mm), z1 = expf(o1 - mm);
        const float inv = 1.f / (z0 + z1);
        out[row * 2]     = z0 * inv;
        out[row * 2 + 1] = z1 * inv;
    }
}

// ============================================================================
extern "C" void kernel_launch(void* const* d_in, const int* in_sizes, int n_in,
                              void* d_out, int out_size) {
    const int*   batch     = (const int*)d_in[0];
    const int*   node_type = (const int*)d_in[1];
    const int*   nbr_type  = (const int*)d_in[2];
    const int*   ext_nbr   = (const int*)d_in[3];
    const float* impact    = (const float*)d_in[4];
    const float* W         = (const float*)d_in[5];
    const float* M         = (const float*)d_in[6];
    const float* U         = (const float*)d_in[7];
    const float* V         = (const float*)d_in[8];
    const float* W1        = (const float*)d_in[9];
    const float* b1        = (const float*)d_in[10];
    const float* W2        = (const float*)d_in[11];
    const float* b2        = (const float*)d_in[12];
    float* out = (float*)d_out;

    cudaFuncSetAttribute(kA, cudaFuncAttributeMaxDynamicSharedMemorySize, SMEM_A);
    cudaFuncSetAttribute(kC, cudaFuncAttributeMaxDynamicSharedMemorySize, SMEM_C);
    cudaFuncSetAttribute(kD, cudaFuncAttributeMaxDynamicSharedMemorySize, SMEM_D);

    kA<<<(NTYPES + 63) / 64, 256, SMEM_A>>>(impact, W, M, W1);
    kB<<<NG, 256>>>(node_type, nbr_type);
    kC<<<(NG + 31) / 32, 256, SMEM_C>>>(U, V, ext_nbr);
    kD<<<NB / 4, 256, SMEM_D>>>(batch, b1, W2, b2, out);
}